// round 7
// baseline (speedup 1.0000x reference)
#include <cuda_runtime.h>
#include <cuda_fp16.h>
#include <cstdint>

// NCC loss, sliding-window, occupancy-3 version.
//
// Block: 256 threads = 8 independent warps; warp owns a 64-px-wide, HS=32-row
// strip (40 row pushes); thread owns 2 adjacent x outputs. Per input row:
//   - row segments (80 floats of I and J incl. x-halo) land in a warp-private
//     4-deep smem staging ring via cp.async.cg 16B with zero-fill for OOB
//     chunks; commit/wait_group 3 keeps loads 3 rows ahead; __syncwarp only.
//   - 9-tap horizontal sums of 5 channels (I, J, I*I, J*J, I*J) from 10
//     LDS.64; products formed in registers.
//   - vertical 9-row sliding sums: 10-deep HALF2 ring in shared memory
//     (51 KB vs 92 KB fp32 -> 3 blocks/SM). Drift-free: run adds the rounded
//     (half) value and subtracts the identical rounded value 9 rows later.
//     Loop unrolled x10 so store slot s and old slot (s+1)%10 are static.
//   - emit: packed-f32x2 cc numer/denom; 2 px combine into one fraction,
//     4 rows share one rcp.approx.
// Finalize fused: double atomicAdd + arrival counter; last block writes the
// mean and resets. ONE launch. 512 blocks -> ~24 resident warps/SM at occ 3.

#define IMG   1024
#define NB    8
#define HS    32
#define TPB   256
#define NWARP 8
#define NPUSH (HS + 8)        // 40 = 4 * 10
#define SEGF  80              // floats staged per warp-row per array
#define NBUF  4               // staging ring depth
#define RSLOT 10              // h-ring depth (>= 9, multiple of unroll)
#define GX    2
#define GY    (IMG / HS)      // 32
#define NBLK  (GX * GY * NB)  // 512

// dynamic smem layout:
//   [0, STG)                staging: [buf][warp][arr][SEGF] floats
//   [STG, STG+RING)         ring:    [slot][ch][tid] half2 (uint32 each)
//   tail                    warpsum[8]
#define STG_FLOATS  (NBUF * NWARP * 2 * SEGF)         // 5120 floats
#define RING_U32    (RSLOT * 5 * TPB)                 // 12800 uint32
#define SMEM_BYTES  ((STG_FLOATS + RING_U32 + 8) * 4) // 71,712 B

typedef unsigned long long ull;

__device__ double       g_accum;
__device__ unsigned int g_cnt;

__device__ __forceinline__ ull pk2(float lo, float hi) {
    ull o;
    asm("mov.b64 %0, {%1, %2};" : "=l"(o)
        : "r"(__float_as_uint(lo)), "r"(__float_as_uint(hi)));
    return o;
}
__device__ __forceinline__ float2 upk2(ull v) {
    unsigned a, b;
    asm("mov.b64 {%0, %1}, %2;" : "=r"(a), "=r"(b) : "l"(v));
    return make_float2(__uint_as_float(a), __uint_as_float(b));
}
#define FADD2(o,a,b)   asm("add.rn.f32x2 %0,%1,%2;"    : "=l"(o) : "l"(a), "l"(b))
#define FMUL2(o,a,b)   asm("mul.rn.f32x2 %0,%1,%2;"    : "=l"(o) : "l"(a), "l"(b))
#define FFMA2(o,a,b,c) asm("fma.rn.f32x2 %0,%1,%2,%3;" : "=l"(o) : "l"(a), "l"(b), "l"(c))

__device__ __forceinline__ void cp16(uint32_t dst, const float* src, uint32_t sz) {
    asm volatile("cp.async.cg.shared.global [%0], [%1], 16, %2;"
                 :: "r"(dst), "l"(src), "r"(sz));
}
#define CP_COMMIT() asm volatile("cp.async.commit_group;" ::: "memory")
#define CP_WAIT3()  asm volatile("cp.async.wait_group 3;" ::: "memory")

__global__ __launch_bounds__(TPB, 3) void ncc_main_kernel(
    const float* __restrict__ I, const float* __restrict__ J,
    float* __restrict__ out)
{
    extern __shared__ __align__(16) float dyn[];
    float* warpsum = dyn + STG_FLOATS + RING_U32;

    const int tid  = threadIdx.x;
    const int lane = tid & 31;
    const int w    = tid >> 5;
    const int W0   = blockIdx.x * 512 + w * 64;
    const int Y0   = blockIdx.y * HS;
    const size_t imgoff = (size_t)blockIdx.z * IMG * IMG;

    uint32_t smem_u32;
    asm("{ .reg .u64 t; cvta.to.shared.u64 t, %1; cvt.u32.u64 %0, t; }"
        : "=r"(smem_u32) : "l"(dyn));

    // ---- per-thread cp.async chunk assignment (fixed across rows)
    // chunks 0..19 -> I floats [W0-8, W0+72); chunks 20..39 -> J same span.
    const bool aIsI = lane < 20;
    const int  ciA  = aIsI ? lane : lane - 20;
    const int  gxA  = W0 - 8 + 4 * ciA;
    const bool vA   = (gxA >= 0) && (gxA <= IMG - 4);
    const float* pbaseA = (aIsI ? I : J) + imgoff + (vA ? gxA : 0);
    const uint32_t dstA0 = smem_u32 + ((w * 2 + (aIsI ? 0 : 1)) * SEGF + 4 * ciA) * 4;

    const bool hasB = lane < 8;                // chunks 32..39 -> J 12..19
    const int  ciB  = 12 + lane;
    const int  gxB  = W0 - 8 + 4 * ciB;
    const bool vB   = (gxB >= 0) && (gxB <= IMG - 4);
    const float* pbaseB = J + imgoff + (vB ? gxB : 0);
    const uint32_t dstB0 = smem_u32 + ((w * 2 + 1) * SEGF + 4 * ciB) * 4;

    const uint32_t BUFSTRIDE = NWARP * 2 * SEGF * 4;   // 5120 bytes

    // ---- half2 ring base for this thread
    uint32_t* ringT = (uint32_t*)(dyn + STG_FLOATS) + tid;
#pragma unroll
    for (int s = 0; s < RSLOT; s++)
#pragma unroll
        for (int c = 0; c < 5; c++)
            ringT[(s * 5 + c) * TPB] = 0u;

    // ---- packed constants / running sums
    const ull NEG1   = pk2(-1.0f, -1.0f);
    const ull MINV81 = pk2(-1.0f / 81.0f, -1.0f / 81.0f);
    const ull EPS2   = pk2(1e-5f, 1e-5f);
    ull run[5];
#pragma unroll
    for (int c = 0; c < 5; c++) run[c] = 0ull;

    float acc = 0.f, gn = 0.f, gd = 1.f;

    // ---- stage helper: push index rr -> input row Y0-4+rr (clamped, zfill)
    auto stage = [&](int rr) {
        const int yin  = Y0 - 4 + rr;
        const bool yok = (unsigned)yin < (unsigned)IMG;
        const int  yc  = min(max(yin, 0), IMG - 1);       // valid addr always
        const uint32_t off  = (uint32_t)yc << 10;         // yc * IMG
        const uint32_t boff = (uint32_t)(rr & (NBUF - 1)) * BUFSTRIDE;
        cp16(dstA0 + boff, pbaseA + off, (yok && vA) ? 16u : 0u);
        if (hasB)
            cp16(dstB0 + boff, pbaseB + off, (yok && vB) ? 16u : 0u);
        CP_COMMIT();
    };

    // ---- prologue: fill pipeline 3 deep
    stage(0); stage(1); stage(2);

#pragma unroll 1
    for (int m = 0; m < NPUSH / RSLOT; m++) {
#pragma unroll
        for (int s = 0; s < RSLOT; s++) {
            const int r = RSLOT * m + s;       // push index; store slot == s

            if (r + 3 < NPUSH) stage(r + 3);
            else               CP_COMMIT();
            CP_WAIT3();
            __syncwarp();

            // ---- horizontal 9-tap sums for 2 adjacent pixels
            const int buf = r & (NBUF - 1);
            const float2* fI = (const float2*)(dyn + (buf * NWARP + w) * 2 * SEGF);
            const float2* fJ = fI + SEGF / 2;
            float2 a0 = fI[lane + 2], a1 = fI[lane + 3], a2 = fI[lane + 4],
                   a3 = fI[lane + 5], a4 = fI[lane + 6];
            float2 b0 = fJ[lane + 2], b1 = fJ[lane + 3], b2 = fJ[lane + 4],
                   b3 = fJ[lane + 5], b4 = fJ[lane + 6];
            float vi[10] = {a0.x, a0.y, a1.x, a1.y, a2.x,
                            a2.y, a3.x, a3.y, a4.x, a4.y};
            float vj[10] = {b0.x, b0.y, b1.x, b1.y, b2.x,
                            b2.y, b3.x, b3.y, b4.x, b4.y};
            float mI = 0.f, mJ = 0.f, mI2 = 0.f, mJ2 = 0.f, mIJ = 0.f;
#pragma unroll
            for (int k = 1; k < 9; k++) {      // shared middle taps 1..8
                float x = vi[k], y = vj[k];
                mI += x; mJ += y;
                mI2 = fmaf(x, x, mI2);
                mJ2 = fmaf(y, y, mJ2);
                mIJ = fmaf(x, y, mIJ);
            }
            float h0[5], h1[5];
            h0[0] = mI + vi[0];               h1[0] = mI + vi[9];
            h0[1] = mJ + vj[0];               h1[1] = mJ + vj[9];
            h0[2] = fmaf(vi[0], vi[0], mI2);  h1[2] = fmaf(vi[9], vi[9], mI2);
            h0[3] = fmaf(vj[0], vj[0], mJ2);  h1[3] = fmaf(vj[9], vj[9], mJ2);
            h0[4] = fmaf(vi[0], vj[0], mIJ);  h1[4] = fmaf(vi[9], vj[9], mIJ);

            // ---- half2 ring, drift-free: add the rounded value; subtract
            // the identical rounded value 9 rows later (old slot (s+1)%10).
#pragma unroll
            for (int c = 0; c < 5; c++) {
                uint32_t oldu = ringT[(((s + 1) % RSLOT) * 5 + c) * TPB];
                __half2  hh   = __floats2half2_rn(h0[c], h1[c]);
                ringT[(s * 5 + c) * TPB] = *(uint32_t*)&hh;
                __half2  oh   = *(__half2*)&oldu;
                ull hr = pk2(__low2float(hh), __high2float(hh));
                ull od = pk2(__low2float(oh), __high2float(oh));
                FADD2(run[c], run[c], hr);
                FFMA2(run[c], od, NEG1, run[c]);
            }

            // ---- emit output row oy = Y0 + (r - 8), both px packed
            if (r >= 8) {
                ull t, u, cross2, iv2, jv2, n2, d2;
                FMUL2(t, run[0], MINV81);          // -si/81
                FFMA2(cross2, t, run[1], run[4]);  // SIJ - si*sj/81
                FFMA2(iv2,    t, run[0], run[2]);  // SI2 - si^2/81
                FMUL2(u, run[1], MINV81);          // -sj/81
                FFMA2(jv2,    u, run[1], run[3]);  // SJ2 - sj^2/81
                FMUL2(n2, cross2, cross2);
                FFMA2(d2, iv2, jv2, EPS2);
                float2 n = upk2(n2), d = upk2(d2);
                float rowN = fmaf(n.x, d.y, n.y * d.x);
                float rowD = d.x * d.y;
                int cnt = (r - 8) & 3;
                if (cnt == 0) { gn = rowN; gd = rowD; }
                else          { gn = fmaf(gn, rowD, rowN * gd); gd *= rowD; }
                if (cnt == 3) {
                    float rc;
                    asm("rcp.approx.f32 %0, %1;" : "=f"(rc) : "f"(gd));
                    acc = fmaf(gn, rc, acc);
                }
            }
        }
    }

    // ---- block reduction + fused finalize
#pragma unroll
    for (int off = 16; off > 0; off >>= 1)
        acc += __shfl_down_sync(0xFFFFFFFFu, acc, off);
    if (lane == 0) warpsum[w] = acc;
    __syncthreads();
    if (tid == 0) {
        float v = 0.f;
#pragma unroll
        for (int i = 0; i < NWARP; i++) v += warpsum[i];
        atomicAdd(&g_accum, (double)v);
        __threadfence();
        unsigned prev = atomicAdd(&g_cnt, 1u);
        if (prev == NBLK - 1) {              // last block finalizes + resets
            double tot = atomicAdd(&g_accum, 0.0);
            out[0] = (float)(tot / (double)((size_t)NB * IMG * IMG));
            g_accum = 0.0;
            g_cnt   = 0u;
        }
    }
}

extern "C" void kernel_launch(void* const* d_in, const int* in_sizes, int n_in,
                              void* d_out, int out_size) {
    const float* I = (const float*)d_in[0];
    const float* J = (const float*)d_in[1];
    float* out = (float*)d_out;

    cudaFuncSetAttribute(ncc_main_kernel,
                         cudaFuncAttributeMaxDynamicSharedMemorySize, SMEM_BYTES);
    dim3 grid(GX, GY, NB);
    ncc_main_kernel<<<grid, TPB, SMEM_BYTES>>>(I, J, out);
}

// round 9
// speedup vs baseline: 1.1182x; 1.1182x over previous
#include <cuda_runtime.h>
#include <cuda_fp16.h>
#include <cstdint>

// NCC loss, sliding-window, full-residency (occ-7) version.
//
// Block: 128 threads = 4 independent warps; warp owns a 64-px-wide, HS=32-row
// strip (40 row pushes); thread owns 2 adjacent x outputs. Per input row:
//   - row segments (72 floats of I and J incl. x-halo) land in a warp-private
//     4-deep smem staging ring via cp.async.cg 16B with zero-fill for OOB
//     chunks; commit/wait_group 3 keeps loads 3 rows ahead; __syncwarp only.
//   - 9-tap horizontal sums of 5 channels (I, J, I*I, J*J, I*J) from 10
//     LDS.64; products formed in registers.
//   - vertical 9-row sliding sums: 9-deep HALF2 ring in smem; old value is
//     read from and the new stored to the SAME slot (r mod 9). run adds the
//     fp32 h and subtracts the half-rounded value 9 rows later; residuals are
//     round-to-nearest noise that cancels in the global mean.
//   - slot indices are compile-time: peel 4 pushes (slots 0..3), then 4 x
//     unroll-9 (slot = (4+s) % 9).
//   - emit: packed-f32x2 cc numer/denom; 2 px combine into one fraction,
//     4 rows share one rcp.approx.
// 1024 blocks x ~30 KB smem -> 7 blocks/SM: ALL 4096 warps resident, single
// wave, no tail. Finalize fused via double atomicAdd + arrival counter.

#define IMG   1024
#define NB    8
#define HS    32
#define TPB   128
#define NWB   4               // warps per block
#define NPUSH (HS + 8)        // 40 = 4 + 4*9
#define SEGF  72              // floats staged per warp-row per array
#define NBUF  4               // staging ring depth
#define RSLOT 9               // vertical h-ring depth
#define GX    4               // x: 4 blocks of (4 warps x 64 px) = 1024
#define GY    (IMG / HS)      // 32
#define NBLK  (GX * GY * NB)  // 1024

// dynamic smem layout:
//   [0, STG)          staging: [buf][warp][arr][SEGF] floats   (9216 B)
//   [STG, STG+RING)   ring:    [slot][ch][tid] half2/u32       (23040 B)
//   tail              warpsum[4]
#define STG_FLOATS  (NBUF * NWB * 2 * SEGF)            // 2304
#define RING_U32    (RSLOT * 5 * TPB)                  // 5760
#define SMEM_BYTES  ((STG_FLOATS + RING_U32 + 4) * 4)  // 32272 B

typedef unsigned long long ull;

__device__ double       g_accum;
__device__ unsigned int g_cnt;

__device__ __forceinline__ ull pk2(float lo, float hi) {
    ull o;
    asm("mov.b64 %0, {%1, %2};" : "=l"(o)
        : "r"(__float_as_uint(lo)), "r"(__float_as_uint(hi)));
    return o;
}
__device__ __forceinline__ float2 upk2(ull v) {
    unsigned a, b;
    asm("mov.b64 {%0, %1}, %2;" : "=r"(a), "=r"(b) : "l"(v));
    return make_float2(__uint_as_float(a), __uint_as_float(b));
}
#define FADD2(o,a,b)   asm("add.rn.f32x2 %0,%1,%2;"    : "=l"(o) : "l"(a), "l"(b))
#define FMUL2(o,a,b)   asm("mul.rn.f32x2 %0,%1,%2;"    : "=l"(o) : "l"(a), "l"(b))
#define FFMA2(o,a,b,c) asm("fma.rn.f32x2 %0,%1,%2,%3;" : "=l"(o) : "l"(a), "l"(b), "l"(c))

__device__ __forceinline__ void cp16(uint32_t dst, const float* src, uint32_t sz) {
    asm volatile("cp.async.cg.shared.global [%0], [%1], 16, %2;"
                 :: "r"(dst), "l"(src), "r"(sz));
}
#define CP_COMMIT() asm volatile("cp.async.commit_group;" ::: "memory")
#define CP_WAIT3()  asm volatile("cp.async.wait_group 3;" ::: "memory")

__global__ __launch_bounds__(TPB, 7) void ncc_main_kernel(
    const float* __restrict__ I, const float* __restrict__ J,
    float* __restrict__ out)
{
    extern __shared__ __align__(16) float dyn[];
    float* warpsum = dyn + STG_FLOATS + RING_U32;

    const int tid  = threadIdx.x;
    const int lane = tid & 31;
    const int w    = tid >> 5;
    const int W0   = blockIdx.x * 256 + w * 64;
    const int Y0   = blockIdx.y * HS;
    const size_t imgoff = (size_t)blockIdx.z * IMG * IMG;

    uint32_t smem_u32;
    asm("{ .reg .u64 t; cvta.to.shared.u64 t, %1; cvt.u32.u64 %0, t; }"
        : "=r"(smem_u32) : "l"(dyn));

    // ---- per-thread cp.async chunk assignment (fixed across rows)
    // segment = floats [W0-4, W0+68) per array: 18 float4 chunks per array.
    // chunk A: lanes 0..17 -> I chunks 0..17; lanes 18..31 -> J chunks 0..13.
    // chunk B: lanes 0..3  -> J chunks 14..17.
    const bool aIsI = lane < 18;
    const int  ciA  = aIsI ? lane : lane - 18;
    const int  gxA  = W0 - 4 + 4 * ciA;
    const bool vA   = (gxA >= 0) && (gxA <= IMG - 4);
    const float* pbaseA = (aIsI ? I : J) + imgoff + (vA ? gxA : 0);
    const uint32_t dstA0 = smem_u32 + ((w * 2 + (aIsI ? 0 : 1)) * SEGF + 4 * ciA) * 4;

    const bool hasB = lane < 4;
    const int  ciB  = 14 + lane;
    const int  gxB  = W0 - 4 + 4 * ciB;
    const bool vB   = (gxB >= 0) && (gxB <= IMG - 4);
    const float* pbaseB = J + imgoff + (vB ? gxB : 0);
    const uint32_t dstB0 = smem_u32 + ((w * 2 + 1) * SEGF + 4 * ciB) * 4;

    const uint32_t BUFSTRIDE = NWB * 2 * SEGF * 4;     // 2304 bytes

    // ---- half2 vertical ring base for this thread
    uint32_t* ringT = (uint32_t*)(dyn + STG_FLOATS) + tid;
#pragma unroll
    for (int s = 0; s < RSLOT; s++)
#pragma unroll
        for (int c = 0; c < 5; c++)
            ringT[(s * 5 + c) * TPB] = 0u;

    // ---- packed constants / running sums
    const ull NEG1   = pk2(-1.0f, -1.0f);
    const ull MINV81 = pk2(-1.0f / 81.0f, -1.0f / 81.0f);
    const ull EPS2   = pk2(1e-5f, 1e-5f);
    ull run[5];
#pragma unroll
    for (int c = 0; c < 5; c++) run[c] = 0ull;

    float acc = 0.f, gn = 0.f, gd = 1.f;

    // ---- stage: push index rr -> input row Y0-4+rr (clamped addr, zfill)
    auto stage = [&](int rr) {
        const int yin  = Y0 - 4 + rr;
        const bool yok = (unsigned)yin < (unsigned)IMG;
        const int  yc  = min(max(yin, 0), IMG - 1);
        const uint32_t off  = (uint32_t)yc << 10;       // yc * IMG
        const uint32_t boff = (uint32_t)(rr & (NBUF - 1)) * BUFSTRIDE;
        cp16(dstA0 + boff, pbaseA + off, (yok && vA) ? 16u : 0u);
        if (hasB)
            cp16(dstB0 + boff, pbaseB + off, (yok && vB) ? 16u : 0u);
        CP_COMMIT();
    };

    // ---- per-push body; slot is a compile-time constant at every call site
    auto body = [&](int r, int slot, bool emitOK) {
        if (r + 3 < NPUSH) stage(r + 3);
        else               CP_COMMIT();
        CP_WAIT3();
        __syncwarp();

        // horizontal 9-tap sums for 2 adjacent pixels
        const int buf = r & (NBUF - 1);
        const float2* fI = (const float2*)(dyn + (buf * NWB + w) * 2 * SEGF);
        const float2* fJ = fI + SEGF / 2;
        float2 a0 = fI[lane], a1 = fI[lane + 1], a2 = fI[lane + 2],
               a3 = fI[lane + 3], a4 = fI[lane + 4];
        float2 b0 = fJ[lane], b1 = fJ[lane + 1], b2 = fJ[lane + 2],
               b3 = fJ[lane + 3], b4 = fJ[lane + 4];
        float vi[10] = {a0.x, a0.y, a1.x, a1.y, a2.x,
                        a2.y, a3.x, a3.y, a4.x, a4.y};
        float vj[10] = {b0.x, b0.y, b1.x, b1.y, b2.x,
                        b2.y, b3.x, b3.y, b4.x, b4.y};
        float mI = 0.f, mJ = 0.f, mI2 = 0.f, mJ2 = 0.f, mIJ = 0.f;
#pragma unroll
        for (int k = 1; k < 9; k++) {       // shared middle taps 1..8
            float x = vi[k], y = vj[k];
            mI += x; mJ += y;
            mI2 = fmaf(x, x, mI2);
            mJ2 = fmaf(y, y, mJ2);
            mIJ = fmaf(x, y, mIJ);
        }
        float h0[5], h1[5];
        h0[0] = mI + vi[0];               h1[0] = mI + vi[9];
        h0[1] = mJ + vj[0];               h1[1] = mJ + vj[9];
        h0[2] = fmaf(vi[0], vi[0], mI2);  h1[2] = fmaf(vi[9], vi[9], mI2);
        h0[3] = fmaf(vj[0], vj[0], mJ2);  h1[3] = fmaf(vj[9], vj[9], mJ2);
        h0[4] = fmaf(vi[0], vj[0], mIJ);  h1[4] = fmaf(vi[9], vj[9], mIJ);

        // vertical ring: same slot holds the 9-rows-ago value. run adds the
        // fp32 h, subtracts the half-rounded old (residual = RN noise).
#pragma unroll
        for (int c = 0; c < 5; c++) {
            uint32_t* rp   = ringT + (slot * 5 + c) * TPB;
            uint32_t  oldu = *rp;                     // LDS (9 rows ago)
            __half2   hh   = __floats2half2_rn(h0[c], h1[c]);
            *rp = *(uint32_t*)&hh;                    // STS (same addr)
            __half2   oh   = *(__half2*)&oldu;
            ull od = pk2(__low2float(oh), __high2float(oh));
            ull h2 = pk2(h0[c], h1[c]);
            FADD2(run[c], run[c], h2);
            FFMA2(run[c], od, NEG1, run[c]);
        }

        // emit output row oy = Y0 + (r - 8), both px packed
        if (emitOK) {
            ull t, u, cross2, iv2, jv2, n2, d2;
            FMUL2(t, run[0], MINV81);          // -si/81
            FFMA2(cross2, t, run[1], run[4]);  // SIJ - si*sj/81
            FFMA2(iv2,    t, run[0], run[2]);  // SI2 - si^2/81
            FMUL2(u, run[1], MINV81);          // -sj/81
            FFMA2(jv2,    u, run[1], run[3]);  // SJ2 - sj^2/81
            FMUL2(n2, cross2, cross2);
            FFMA2(d2, iv2, jv2, EPS2);
            float2 n = upk2(n2), d = upk2(d2);
            float rowN = fmaf(n.x, d.y, n.y * d.x);
            float rowD = d.x * d.y;
            int cnt = (r - 8) & 3;
            if (cnt == 0) { gn = rowN; gd = rowD; }
            else          { gn = fmaf(gn, rowD, rowN * gd); gd *= rowD; }
            if (cnt == 3) {
                float rc;
                asm("rcp.approx.f32 %0, %1;" : "=f"(rc) : "f"(gd));
                acc = fmaf(gn, rc, acc);
            }
        }
    };

    // ---- prologue: fill pipeline 3 deep, then peel pushes 0..3 (no emit)
    stage(0); stage(1); stage(2);
    body(0, 0, false);
    body(1, 1, false);
    body(2, 2, false);
    body(3, 3, false);

    // ---- main: 4 x unroll-9; slot = (4+s) % 9 is compile-time
#pragma unroll 1
    for (int m = 0; m < 4; m++) {
#pragma unroll
        for (int s = 0; s < 9; s++) {
            const int r = 4 + 9 * m + s;
            const bool emitOK = (s >= 4) ? true : (m > 0);
            body(r, (4 + s) % 9, emitOK);
        }
    }

    // ---- block reduction + fused finalize
#pragma unroll
    for (int off = 16; off > 0; off >>= 1)
        acc += __shfl_down_sync(0xFFFFFFFFu, acc, off);
    if (lane == 0) warpsum[w] = acc;
    __syncthreads();
    if (tid == 0) {
        float v = warpsum[0] + warpsum[1] + warpsum[2] + warpsum[3];
        atomicAdd(&g_accum, (double)v);
        __threadfence();
        unsigned prev = atomicAdd(&g_cnt, 1u);
        if (prev == NBLK - 1) {              // last block finalizes + resets
            double tot = atomicAdd(&g_accum, 0.0);
            out[0] = (float)(tot / (double)((size_t)NB * IMG * IMG));
            g_accum = 0.0;
            g_cnt   = 0u;
        }
    }
}

extern "C" void kernel_launch(void* const* d_in, const int* in_sizes, int n_in,
                              void* d_out, int out_size) {
    const float* I = (const float*)d_in[0];
    const float* J = (const float*)d_in[1];
    float* out = (float*)d_out;

    cudaFuncSetAttribute(ncc_main_kernel,
                         cudaFuncAttributeMaxDynamicSharedMemorySize, SMEM_BYTES);
    dim3 grid(GX, GY, NB);
    ncc_main_kernel<<<grid, TPB, SMEM_BYTES>>>(I, J, out);
}

// round 11
// speedup vs baseline: 1.2695x; 1.1352x over previous
#include <cuda_runtime.h>
#include <cuda_fp16.h>
#include <cstdint>

// NCC loss, sliding-window, 4-pixels-per-thread version.
//
// Block: 128 threads = 4 independent warps; warp owns a 128-px-wide, HS=32-row
// strip (40 row pushes); thread owns 4 adjacent x outputs (x0 = W0 + 4*lane).
// Per input row:
//   - row segments (136 floats of I and J incl. x-halo) land in a warp-private
//     2-deep smem staging ring via cp.async.cg 16B (zero-fill for OOB chunks);
//     distance-1 prefetch, wait_group 1, __syncwarp only.
//   - 9-tap horizontal sums of 5 channels for 4 px from 3+3 LDS.128 via a
//     shared-core scheme: core = taps 3..8, mids m01/m23, 4 edge adds.
//   - vertical 9-row sliding sums: 9-deep ring in smem, one 8-byte entry
//     (2 x half2 = 4 px) per channel: LDS.64 + STS.64 move all 4 px.
//     run (packed f32x2, one per pixel-pair) adds the fp32 h and subtracts
//     the half-rounded value 9 rows later (RN noise, cancels in the mean).
//   - emit: packed-f32x2 cc per pixel-pair; per-pair fractions grouped over
//     4 rows -> one rcp.approx per 8 px.
// 512 blocks x 54.8 KB smem -> 4 blocks/SM: single wave, all warps resident.
// Finalize fused via double atomicAdd + arrival counter. ONE launch.

#define IMG   1024
#define NB    8
#define HS    32
#define TPB   128
#define NWB   4
#define NPUSH (HS + 8)        // 40 = 4 + 4*9
#define SEGF  136             // floats staged per warp-row per array
#define NBUF  2               // staging ring depth
#define RSLOT 9
#define GX    2               // 2 x (4 warps x 128 px) = 1024
#define GY    (IMG / HS)      // 32
#define NBLK  (GX * GY * NB)  // 512

// dynamic smem:
//   [0, STG)        staging: [buf][warp][arr][SEGF] floats     (8704 B)
//   [STG, +RING)    ring:    [slot][ch][tid] 8B (2 x half2)    (46080 B)
//   tail            warpsum[4]
#define STG_FLOATS (NBUF * NWB * 2 * SEGF)               // 2176
#define RING_U64   (RSLOT * 5 * TPB)                     // 5760
#define SMEM_BYTES ((STG_FLOATS + 2 * RING_U64 + 4) * 4) // 54800 B

typedef unsigned long long ull;

__device__ double       g_accum;
__device__ unsigned int g_cnt;

__device__ __forceinline__ ull pk2(float lo, float hi) {
    ull o;
    asm("mov.b64 %0, {%1, %2};" : "=l"(o)
        : "r"(__float_as_uint(lo)), "r"(__float_as_uint(hi)));
    return o;
}
__device__ __forceinline__ float2 upk2(ull v) {
    unsigned a, b;
    asm("mov.b64 {%0, %1}, %2;" : "=r"(a), "=r"(b) : "l"(v));
    return make_float2(__uint_as_float(a), __uint_as_float(b));
}
#define FADD2(o,a,b)   asm("add.rn.f32x2 %0,%1,%2;"    : "=l"(o) : "l"(a), "l"(b))
#define FMUL2(o,a,b)   asm("mul.rn.f32x2 %0,%1,%2;"    : "=l"(o) : "l"(a), "l"(b))
#define FFMA2(o,a,b,c) asm("fma.rn.f32x2 %0,%1,%2,%3;" : "=l"(o) : "l"(a), "l"(b), "l"(c))

__device__ __forceinline__ void cp16(uint32_t dst, const float* src, uint32_t sz) {
    asm volatile("cp.async.cg.shared.global [%0], [%1], 16, %2;"
                 :: "r"(dst), "l"(src), "r"(sz));
}
#define CP_COMMIT() asm volatile("cp.async.commit_group;" ::: "memory")
#define CP_WAIT1()  asm volatile("cp.async.wait_group 1;" ::: "memory")

__global__ __launch_bounds__(TPB, 4) void ncc_main_kernel(
    const float* __restrict__ I, const float* __restrict__ J,
    float* __restrict__ out)
{
    extern __shared__ __align__(16) float dyn[];
    float* warpsum = dyn + STG_FLOATS + 2 * RING_U64;

    const int tid  = threadIdx.x;
    const int lane = tid & 31;
    const int w    = tid >> 5;
    const int W0   = blockIdx.x * 512 + w * 128;
    const int Y0   = blockIdx.y * HS;
    const size_t imgoff = (size_t)blockIdx.z * IMG * IMG;

    uint32_t smem_u32;
    asm("{ .reg .u64 t; cvta.to.shared.u64 t, %1; cvt.u32.u64 %0, t; }"
        : "=r"(smem_u32) : "l"(dyn));

    // ---- cp.async chunk assignment: per warp-row, 34 float4 chunks per
    // array (floats [W0-4, W0+132)); 68 chunks total across I then J.
    //   A: lanes 0..31 -> chunk lane        (I 0..31)
    //   B: lanes 0..31 -> chunk 32+lane     (I 32,33 then J 0..29)
    //   C: lanes 0..3  -> chunk 64+lane     (J 30..33)
    const int  cA   = lane;            // array I, chunk lane
    const int  gxA  = W0 - 4 + 4 * cA;
    const bool vAok = (gxA >= 0) && (gxA <= IMG - 4);
    const float* pbaseA = I + imgoff + (vAok ? gxA : 0);
    const uint32_t dstA0 = smem_u32 + ((w * 2 + 0) * SEGF + 4 * cA) * 4;

    const bool bIsI = lane < 2;        // chunks 32,33 are I
    const int  cB   = bIsI ? (32 + lane) : (lane - 2);
    const int  gxB  = W0 - 4 + 4 * cB;
    const bool vBok = (gxB >= 0) && (gxB <= IMG - 4);
    const float* pbaseB = (bIsI ? I : J) + imgoff + (vBok ? gxB : 0);
    const uint32_t dstB0 = smem_u32 + ((w * 2 + (bIsI ? 0 : 1)) * SEGF + 4 * cB) * 4;

    const bool hasC = lane < 4;
    const int  cC   = 30 + lane;       // J chunks 30..33
    const int  gxC  = W0 - 4 + 4 * cC;
    const bool vCok = (gxC >= 0) && (gxC <= IMG - 4);
    const float* pbaseC = J + imgoff + (vCok ? gxC : 0);
    const uint32_t dstC0 = smem_u32 + ((w * 2 + 1) * SEGF + 4 * cC) * 4;

    const uint32_t BUFSTRIDE = NWB * 2 * SEGF * 4;   // 4352 bytes

    // ---- vertical ring base (one 8B entry = 4 px as 2 x half2)
    ull* ringT = (ull*)(dyn + STG_FLOATS) + tid;
#pragma unroll
    for (int s = 0; s < RSLOT; s++)
#pragma unroll
        for (int c = 0; c < 5; c++)
            ringT[(s * 5 + c) * TPB] = 0ull;

    // ---- constants / state
    const ull NEG1   = pk2(-1.0f, -1.0f);
    const ull MINV81 = pk2(-1.0f / 81.0f, -1.0f / 81.0f);
    const ull EPS2   = pk2(1e-5f, 1e-5f);
    ull run[5][2];                        // [channel][pixel-pair]
#pragma unroll
    for (int c = 0; c < 5; c++) { run[c][0] = 0ull; run[c][1] = 0ull; }

    float acc = 0.f;
    float gn[2] = {0.f, 0.f}, gd[2] = {1.f, 1.f};

    // ---- stage: push rr -> input row Y0-4+rr (clamped addr, zero-fill OOB)
    auto stage = [&](int rr) {
        const int yin  = Y0 - 4 + rr;
        const bool yok = (unsigned)yin < (unsigned)IMG;
        const int  yc  = min(max(yin, 0), IMG - 1);
        const uint32_t off  = (uint32_t)yc << 10;
        const uint32_t boff = (uint32_t)(rr & (NBUF - 1)) * BUFSTRIDE;
        cp16(dstA0 + boff, pbaseA + off, (yok && vAok) ? 16u : 0u);
        cp16(dstB0 + boff, pbaseB + off, (yok && vBok) ? 16u : 0u);
        if (hasC)
            cp16(dstC0 + boff, pbaseC + off, (yok && vCok) ? 16u : 0u);
        CP_COMMIT();
    };

    // ---- per-push body; slot compile-time at every call site
    auto body = [&](int r, int slot, bool emitOK) {
        if (r + 1 < NPUSH) stage(r + 1);
        else               CP_COMMIT();
        CP_WAIT1();
        __syncwarp();

        // 12-float windows (4 px) from 3 LDS.128 per array
        const int buf = r & (NBUF - 1);
        const float4* fI4 = (const float4*)(dyn + (buf * NWB + w) * 2 * SEGF);
        const float4* fJ4 = fI4 + SEGF / 4;
        float4 ia = fI4[lane], ib = fI4[lane + 1], ic = fI4[lane + 2];
        float4 ja = fJ4[lane], jb = fJ4[lane + 1], jc = fJ4[lane + 2];
        float vi[12] = {ia.x, ia.y, ia.z, ia.w, ib.x, ib.y,
                        ib.z, ib.w, ic.x, ic.y, ic.z, ic.w};
        float vj[12] = {ja.x, ja.y, ja.z, ja.w, jb.x, jb.y,
                        jb.z, jb.w, jc.x, jc.y, jc.z, jc.w};

        // shared-core horizontal 9-tap sums for 4 px:
        //   core = taps 3..8 ; m01 = core+t1+t2 ; m23 = core+t9+t10
        //   h0=m01+t0  h1=m01+t9  h2=m23+t2  h3=m23+t11
        float h[5][4];
#pragma unroll
        for (int c = 0; c < 5; c++) {
            auto tap = [&](int k) -> float {
                return (c == 0) ? vi[k]
                     : (c == 1) ? vj[k]
                     : (c == 2) ? vi[k] * vi[k]
                     : (c == 3) ? vj[k] * vj[k]
                                : vi[k] * vj[k];
            };
            float core = tap(3) + tap(4) + tap(5) + tap(6) + tap(7) + tap(8);
            float m01  = core + tap(1) + tap(2);
            float m23  = core + tap(9) + tap(10);
            h[c][0] = m01 + tap(0);
            h[c][1] = m01 + tap(9);
            h[c][2] = m23 + tap(2);
            h[c][3] = m23 + tap(11);
        }

        // vertical ring: 8B entry = 2 x half2 (4 px). run adds fp32 h,
        // subtracts the half-rounded value 9 rows later.
#pragma unroll
        for (int c = 0; c < 5; c++) {
            ull* rp  = ringT + (slot * 5 + c) * TPB;
            ull  old = *rp;                               // LDS.64
            __half2 nlo = __floats2half2_rn(h[c][0], h[c][1]);
            __half2 nhi = __floats2half2_rn(h[c][2], h[c][3]);
            ull nw;
            asm("mov.b64 %0, {%1, %2};" : "=l"(nw)
                : "r"(*(uint32_t*)&nlo), "r"(*(uint32_t*)&nhi));
            *rp = nw;                                     // STS.64
            uint32_t olo, ohi;
            asm("mov.b64 {%0, %1}, %2;" : "=r"(olo), "=r"(ohi) : "l"(old));
            float2 o01 = __half22float2(*(__half2*)&olo);
            float2 o23 = __half22float2(*(__half2*)&ohi);
            ull od0 = pk2(o01.x, o01.y);
            ull od1 = pk2(o23.x, o23.y);
            ull h01 = pk2(h[c][0], h[c][1]);
            ull h23 = pk2(h[c][2], h[c][3]);
            FADD2(run[c][0], run[c][0], h01);
            FFMA2(run[c][0], od0, NEG1, run[c][0]);
            FADD2(run[c][1], run[c][1], h23);
            FFMA2(run[c][1], od1, NEG1, run[c][1]);
        }

        // emit output row oy = Y0 + (r - 8): per pixel-pair packed cc,
        // pair fractions grouped over 4 rows -> 1 rcp per 8 px.
        if (emitOK) {
            const int cnt = (r - 8) & 3;
#pragma unroll
            for (int p = 0; p < 2; p++) {
                ull t, u, cross2, iv2, jv2, n2, d2;
                FMUL2(t, run[0][p], MINV81);              // -si/81
                FFMA2(cross2, t, run[1][p], run[4][p]);   // SIJ - si*sj/81
                FFMA2(iv2,    t, run[0][p], run[2][p]);   // SI2 - si^2/81
                FMUL2(u, run[1][p], MINV81);              // -sj/81
                FFMA2(jv2,    u, run[1][p], run[3][p]);   // SJ2 - sj^2/81
                FMUL2(n2, cross2, cross2);
                FFMA2(d2, iv2, jv2, EPS2);
                float2 n = upk2(n2), d = upk2(d2);
                float rowN = fmaf(n.x, d.y, n.y * d.x);
                float rowD = d.x * d.y;
                if (cnt == 0) { gn[p] = rowN; gd[p] = rowD; }
                else { gn[p] = fmaf(gn[p], rowD, rowN * gd[p]); gd[p] *= rowD; }
                if (cnt == 3) {
                    float rc;
                    asm("rcp.approx.f32 %0, %1;" : "=f"(rc) : "f"(gd[p]));
                    acc = fmaf(gn[p], rc, acc);
                }
            }
        }
    };

    // ---- prologue: 1-deep prefetch, then peel pushes 0..3 (slots 0..3)
    stage(0);
    body(0, 0, false);
    body(1, 1, false);
    body(2, 2, false);
    body(3, 3, false);

    // ---- main: 4 x unroll-9; slot = (4+s) % 9 compile-time
#pragma unroll 1
    for (int m = 0; m < 4; m++) {
#pragma unroll
        for (int s = 0; s < 9; s++) {
            const int r = 4 + 9 * m + s;
            const bool emitOK = (s >= 4) ? true : (m > 0);
            body(r, (4 + s) % 9, emitOK);
        }
    }

    // ---- block reduction + fused finalize
#pragma unroll
    for (int off = 16; off > 0; off >>= 1)
        acc += __shfl_down_sync(0xFFFFFFFFu, acc, off);
    if (lane == 0) warpsum[w] = acc;
    __syncthreads();
    if (tid == 0) {
        float v = warpsum[0] + warpsum[1] + warpsum[2] + warpsum[3];
        atomicAdd(&g_accum, (double)v);
        __threadfence();
        unsigned prev = atomicAdd(&g_cnt, 1u);
        if (prev == NBLK - 1) {               // last block finalizes + resets
            double tot = atomicAdd(&g_accum, 0.0);
            out[0] = (float)(tot / (double)((size_t)NB * IMG * IMG));
            g_accum = 0.0;
            g_cnt   = 0u;
        }
    }
}

extern "C" void kernel_launch(void* const* d_in, const int* in_sizes, int n_in,
                              void* d_out, int out_size) {
    const float* I = (const float*)d_in[0];
    const float* J = (const float*)d_in[1];
    float* out = (float*)d_out;

    cudaFuncSetAttribute(ncc_main_kernel,
                         cudaFuncAttributeMaxDynamicSharedMemorySize, SMEM_BYTES);
    dim3 grid(GX, GY, NB);
    ncc_main_kernel<<<grid, TPB, SMEM_BYTES>>>(I, J, out);
}